// round 2
// baseline (speedup 1.0000x reference)
#include <cuda_runtime.h>
#include <math.h>

#define N_NODES_MAX 16384
#define IN_DIM 512
#define MEM_DIM 256
#define VOCAB 64
#define MAX_CH 8

// Scratch (allocation-free rule: __device__ globals)
__device__ float g_X[N_NODES_MAX * MEM_DIM];   // inputs @ W_in^T + b
__device__ float g_P[N_NODES_MAX * MEM_DIM];   // states @ W_ch^T (per level, absolute-indexed)
__device__ float g_D[VOCAB * MEM_DIM];         // deprel_emb @ W_dep^T

// ---------------------------------------------------------------------------
// C[m,n] = sum_k A[m*lda + k] * W[n*1024 + wofs + k]  (+ bias[n])
// Tiled SGEMM: 64x64 block tile, BK=16, 256 threads, 4x4 per thread.
// ---------------------------------------------------------------------------
template<bool HAS_BIAS>
__global__ void gemm_wT(const float* __restrict__ A, int lda,
                        const float* __restrict__ W, int wofs,
                        const float* __restrict__ bias,
                        float* __restrict__ Cmat, int M, int K) {
    __shared__ float As[16][68];   // [k][m]
    __shared__ float Bs[16][68];   // [k][n]

    const int tid = threadIdx.x;           // 0..255
    const int bm  = blockIdx.x * 64;
    const int bn  = blockIdx.y * 64;
    const int tm  = (tid >> 4) * 4;        // 0..60
    const int tn  = (tid & 15) * 4;        // 0..60

    float acc[4][4] = {};

    const int lr  = tid >> 2;              // 0..63 : tile row loaded by this thread
    const int lc4 = (tid & 3) * 4;         // 0,4,8,12 : k offset (float4)

    for (int k0 = 0; k0 < K; k0 += 16) {
        // A tile (64 x 16)
        {
            int gm = bm + lr;
            float4 v = make_float4(0.f, 0.f, 0.f, 0.f);
            if (gm < M)
                v = *(const float4*)(A + (long)gm * lda + k0 + lc4);
            As[lc4 + 0][lr] = v.x; As[lc4 + 1][lr] = v.y;
            As[lc4 + 2][lr] = v.z; As[lc4 + 3][lr] = v.w;
        }
        // B tile (64 x 16): B[n,k] = W[n*1024 + wofs + k]; N=256 always valid
        {
            float4 v = *(const float4*)(W + (long)(bn + lr) * 1024 + wofs + k0 + lc4);
            Bs[lc4 + 0][lr] = v.x; Bs[lc4 + 1][lr] = v.y;
            Bs[lc4 + 2][lr] = v.z; Bs[lc4 + 3][lr] = v.w;
        }
        __syncthreads();

        #pragma unroll
        for (int k = 0; k < 16; ++k) {
            float a0 = As[k][tm+0], a1 = As[k][tm+1], a2 = As[k][tm+2], a3 = As[k][tm+3];
            float b0 = Bs[k][tn+0], b1 = Bs[k][tn+1], b2 = Bs[k][tn+2], b3 = Bs[k][tn+3];
            acc[0][0] += a0*b0; acc[0][1] += a0*b1; acc[0][2] += a0*b2; acc[0][3] += a0*b3;
            acc[1][0] += a1*b0; acc[1][1] += a1*b1; acc[1][2] += a1*b2; acc[1][3] += a1*b3;
            acc[2][0] += a2*b0; acc[2][1] += a2*b1; acc[2][2] += a2*b2; acc[2][3] += a2*b3;
            acc[3][0] += a3*b0; acc[3][1] += a3*b1; acc[3][2] += a3*b2; acc[3][3] += a3*b3;
        }
        __syncthreads();
    }

    #pragma unroll
    for (int u = 0; u < 4; ++u) {
        int gm = bm + tm + u;
        if (gm >= M) continue;
        #pragma unroll
        for (int v = 0; v < 4; ++v) {
            int gn = bn + tn + v;
            float val = acc[u][v];
            if (HAS_BIAS) val += bias[gn];
            Cmat[(long)gm * MEM_DIM + gn] = val;
        }
    }
}

// ---------------------------------------------------------------------------
// Leaves: states[i] = tanh(X[i]) for i in [first_leaf, N)
// ---------------------------------------------------------------------------
__global__ void leaves_k(const float* __restrict__ X, float* __restrict__ S,
                         int first_leaf, int N) {
    long base = (long)first_leaf * MEM_DIM;
    long tot  = (long)N * MEM_DIM - base;
    long idx  = (long)blockIdx.x * blockDim.x + threadIdx.x;
    if (idx < tot) S[base + idx] = tanhf(X[base + idx]);
}

// ---------------------------------------------------------------------------
// Combine: one block per node, 256 threads (one per feature).
// r[k,f] = tanh(X[i,f] + D[cdep,f] + P[child,f]) for real children (prefix of
// length C); pooled out[f] = max_{t<C} flat[f*C + t] over row-major r[:C].
// The reference's min(j//M, K-1) clamp is dead: f*C+t <= 256*C-1 stays inside
// the first C rows, so only real children are ever read.
// ---------------------------------------------------------------------------
__global__ void combine_k(int lo,
                          const int*   __restrict__ cidx,
                          const int*   __restrict__ cdep,
                          const int*   __restrict__ counts,
                          const float* __restrict__ X,
                          const float* __restrict__ D,
                          const float* __restrict__ P,
                          float*       __restrict__ S) {
    const int i = lo + (int)blockIdx.x;
    const int f = threadIdx.x;
    __shared__ float r[MAX_CH * MEM_DIM];

    const int cnt = counts[i];
    const float x = X[(long)i * MEM_DIM + f];

    if (cnt == 0) {               // leaf-style fallback (not expected in this range)
        S[(long)i * MEM_DIM + f] = tanhf(x);
        return;
    }
    const int C = cnt;

    #pragma unroll
    for (int k = 0; k < MAX_CH; ++k) {
        int c = cidx[i * MAX_CH + k];
        if (c >= 0) {
            int dv = cdep[i * MAX_CH + k];
            r[k * MEM_DIM + f] =
                tanhf(x + D[dv * MEM_DIM + f] + P[(long)c * MEM_DIM + f]);
        }
    }
    __syncthreads();

    float m = -3.402823466e38f;
    for (int t = 0; t < C; ++t)
        m = fmaxf(m, r[f * C + t]);

    S[(long)i * MEM_DIM + f] = m;
}

// ---------------------------------------------------------------------------
extern "C" void kernel_launch(void* const* d_in, const int* in_sizes, int n_in,
                              void* d_out, int out_size) {
    const float* inputs    = (const float*)d_in[0];   // [N, 512]
    const float* W         = (const float*)d_in[1];   // [256, 1024]
    const float* bvec      = (const float*)d_in[2];   // [256]
    const float* deprel    = (const float*)d_in[3];   // [64, 256]
    const int*   child_idx = (const int*)  d_in[4];   // [N, 8]
    const int*   child_dep = (const int*)  d_in[5];   // [N, 8]
    const int*   counts    = (const int*)  d_in[6];   // [N]
    float*       states    = (float*)d_out;           // [N, 256]

    float *X = nullptr, *P = nullptr, *D = nullptr;
    cudaGetSymbolAddress((void**)&X, g_X);
    cudaGetSymbolAddress((void**)&P, g_P);
    cudaGetSymbolAddress((void**)&D, g_D);

    const int N = in_sizes[0] / IN_DIM;               // 16384

    // Phase 0: input projection + bias, and deprel projection
    gemm_wT<true ><<<dim3((unsigned)((N + 63) / 64), 4), 256>>>(
        inputs, IN_DIM, W, 0, bvec, X, N, IN_DIM);
    gemm_wT<false><<<dim3(1, 4), 256>>>(
        deprel, MEM_DIM, W, IN_DIM, nullptr, D, VOCAB, MEM_DIM);

    // Phase 1: leaves. Node i is a leaf iff 8i+1 >= N  =>  i >= ceil((N-1)/8)
    const int first_leaf = (N + MAX_CH - 2) / MAX_CH; // 2048 for N=16384
    {
        long tot = (long)(N - first_leaf) * MEM_DIM;
        leaves_k<<<(unsigned)((tot + 255) / 256), 256>>>(X, states, first_leaf, N);
    }

    // Level starts: s[L] = (8^L - 1)/7
    long s[12];
    s[0] = 0;
    int nl = 0;
    while (s[nl] < N) { s[nl + 1] = 8 * s[nl] + 1; nl++; }

    // Phase 2..: internal levels, bottom-up
    for (int L = nl - 1; L >= 0; --L) {
        long lo = s[L];
        long hi = s[L + 1] - 1;
        if (hi > first_leaf - 1) hi = first_leaf - 1;
        if (lo > hi) continue;

        long clo = 8 * lo + 1;
        long chi = 8 * hi + 8;
        if (chi > N - 1) chi = N - 1;
        int Mc = (int)(chi - clo + 1);

        // P[j] = states[j] @ W_ch^T for all children of this level (contiguous range)
        gemm_wT<false><<<dim3((unsigned)((Mc + 63) / 64), 4), 256>>>(
            states + clo * MEM_DIM, MEM_DIM, W, IN_DIM + MEM_DIM, nullptr,
            P + clo * MEM_DIM, Mc, MEM_DIM);

        combine_k<<<(unsigned)(hi - lo + 1), 256>>>(
            (int)lo, child_idx, child_dep, counts, X, D, P, states);
    }
}